// round 16
// baseline (speedup 1.0000x reference)
#include <cuda_runtime.h>
#include <cuda_fp16.h>
#include <math.h>
#include <stdint.h>

#define D_MODEL 1024
#define N_HEAD  16
#define D_HEAD  64
#define N_CTX   2048
#define BATCH   2
#define MTOT    (BATCH * N_CTX)   /* 4096 rows */

// ---------------- scratch ----------------
__device__ __half g_qh[MTOT * D_MODEL];
__device__ __half g_kh[MTOT * D_MODEL];
__device__ __half g_vh[MTOT * D_MODEL];
__device__ __half g_zh[MTOT * D_MODEL];
__device__ __half g_xh[MTOT * D_MODEL];
__device__ __half g_wqh[D_MODEL * D_MODEL];
__device__ __half g_wkh[D_MODEL * D_MODEL];
__device__ __half g_wvh[D_MODEL * D_MODEL];
__device__ __half g_woh[D_MODEL * D_MODEL];
__device__ float  g_cos[N_CTX * 32];
__device__ float  g_sin[N_CTX * 32];

// ---------------- helpers ----------------
__device__ __forceinline__ uint32_t pack2(float x, float y) {
    __half2 h = __floats2half2_rn(x, y);
    return *(uint32_t*)&h;
}

// fp16 m16n8k16
__device__ __forceinline__ void mma16(float c[4], const uint32_t* a, const uint32_t* b) {
    asm volatile(
        "mma.sync.aligned.m16n8k16.row.col.f32.f16.f16.f32 "
        "{%0,%1,%2,%3}, {%4,%5,%6,%7}, {%8,%9}, {%0,%1,%2,%3};\n"
        : "+f"(c[0]), "+f"(c[1]), "+f"(c[2]), "+f"(c[3])
        : "r"(a[0]), "r"(a[1]), "r"(a[2]), "r"(a[3]), "r"(b[0]), "r"(b[1]));
}

// ---------------- RoPE table ----------------
__global__ void rope_cache_kernel() {
    int i = blockIdx.x * blockDim.x + threadIdx.x;
    int t = i >> 5;
    int j = i & 31;
    float invf = (float)pow(10000.0, -(double)j / 32.0);
    double ang = (double)t * (double)invf;
    double sv, cv;
    sincos(ang, &sv, &cv);
    g_cos[i] = (float)cv;
    g_sin[i] = (float)sv;
}

// ---------------- fp32 -> fp16 conversion (x + 4 weight matrices) ----------------
struct CvtJobs {
    const float* src[5];
    __half*      dst[5];
    int          n[5];
};

__global__ __launch_bounds__(256)
void cvt_kernel(CvtJobs j) {
    int z = blockIdx.y;
    int i = (blockIdx.x * 256 + threadIdx.x) * 8;
    if (i >= j.n[z]) return;
    float4 f0 = *(const float4*)(j.src[z] + i);
    float4 f1 = *(const float4*)(j.src[z] + i + 4);
    uint4 o;
    o.x = pack2(f0.x, f0.y); o.y = pack2(f0.z, f0.w);
    o.z = pack2(f1.x, f1.y); o.w = pack2(f1.z, f1.w);
    *(uint4*)(j.dst[z] + i) = o;
}

// ---------------- FP16 GEMM, 128-thread CTA, tile 128x64, double-buffered ----------------
// 4 warps stacked in M; warp tile 32x64. A buffer = attention Qh layout,
// B buffer = attention Kh layout. 3-4 independent CTAs/SM hide LDG latency.
struct GemmJobs {
    const __half* W[3];
    const float*  bias[3];
    const float*  res[3];
    void*         out[3];
    int           norm[3];      // 1 => fused rmsnorm+rope epilogue, half out
    int           outhalf[3];   // 1 => half out
};

__global__ __launch_bounds__(128, 3)
void gemm_fp16_kernel(const __half* __restrict__ A, GemmJobs jobs,
                      const float* __restrict__ nw, int M, int N, int K)
{
    __shared__ __align__(16) uint4 Ah[2][512];   // [ks2][mt8][lane32] 8KB/buf
    __shared__ __align__(16) uint2 Bh[2][512];   // [ks2][nt8][lane32] 4KB/buf

    const int z = blockIdx.z;
    const __half* W   = jobs.W[z];
    const float* bias = jobs.bias[z];
    const float* res  = jobs.res[z];
    const int    donorm = jobs.norm[z];
    const int    ohalf  = jobs.outhalf[z];

    const int tid = threadIdx.x;
    const int lane = tid & 31;
    const int wp = tid >> 5;
    const int g = lane >> 2, t = lane & 3;
    const int m0 = blockIdx.y * 128, n0 = blockIdx.x * 64;

    // A loader: rows {16*amt+ag, +8}, cols adh*16..+15  (adh = ks)
    const int amt = tid >> 4, ag = (tid >> 1) & 7, adh = tid & 1;
    const int ax = ((ag >> 1) & 1) | (adh << 1);
    const __half* Ap = A + (size_t)(m0 + amt * 16 + ag) * K + adh * 16;
    // B loader: row bn, cols bh*16..+15  (bh = ks)
    const int bn = tid >> 1, bh = tid & 1;
    const int bnt = bn >> 3, bg = bn & 7;
    const int bx = (bg >> 2) | (bh << 1);
    const __half* Wp = W + (size_t)(n0 + bn) * K + bh * 16;

    float acc[2][8][4];
#pragma unroll
    for (int mi = 0; mi < 2; mi++)
#pragma unroll
        for (int ni = 0; ni < 8; ni++)
#pragma unroll
            for (int e = 0; e < 4; e++) acc[mi][ni][e] = 0.f;

    const int NCH = K / 32;
    uint4 aA0 = *(const uint4*)(Ap);
    uint4 aB0 = *(const uint4*)(Ap + 8);
    uint4 aA1 = *(const uint4*)(Ap + (size_t)8 * K);
    uint4 aB1 = *(const uint4*)(Ap + (size_t)8 * K + 8);
    uint4 wA  = *(const uint4*)(Wp);
    uint4 wB  = *(const uint4*)(Wp + 8);

    for (int kt = 0; kt < NCH; kt++) {
        const int p = kt & 1;
        {
            const uint32_t* a0 = (const uint32_t*)&aA0;
            const uint32_t* a1 = (const uint32_t*)&aA1;
            const uint32_t* b0 = (const uint32_t*)&aB0;
            const uint32_t* b1 = (const uint32_t*)&aB1;
            const uint32_t* wa = (const uint32_t*)&wA;
            const uint32_t* wb = (const uint32_t*)&wB;
#pragma unroll
            for (int tt = 0; tt < 4; tt++) {
                Ah[p][(adh * 8 + amt) * 32 + ag * 4 + (tt ^ ax)] =
                    make_uint4(a0[tt], a1[tt], b0[tt], b1[tt]);
                Bh[p][(bh * 8 + bnt) * 32 + bg * 4 + (tt ^ bx)] =
                    make_uint2(wa[tt], wb[tt]);
            }
        }
        __syncthreads();
        if (kt + 1 < NCH) {
            int off = (kt + 1) * 32;
            aA0 = *(const uint4*)(Ap + off);
            aB0 = *(const uint4*)(Ap + off + 8);
            aA1 = *(const uint4*)(Ap + off + (size_t)8 * K);
            aB1 = *(const uint4*)(Ap + off + (size_t)8 * K + 8);
            wA  = *(const uint4*)(Wp + off);
            wB  = *(const uint4*)(Wp + off + 8);
        }
#pragma unroll
        for (int ks = 0; ks < 2; ks++) {
            int xb = (g >> 2) | (ks << 1);
            uint2 bb[8];
#pragma unroll
            for (int ni = 0; ni < 8; ni++)
                bb[ni] = Bh[p][(ks * 8 + ni) * 32 + g * 4 + (t ^ xb)];
            int xa = ((g >> 1) & 1) | (ks << 1);
            uint4 aa[2];
#pragma unroll
            for (int mi = 0; mi < 2; mi++)
                aa[mi] = Ah[p][(ks * 8 + wp * 2 + mi) * 32 + g * 4 + (t ^ xa)];
#pragma unroll
            for (int mi = 0; mi < 2; mi++)
#pragma unroll
                for (int ni = 0; ni < 8; ni++)
                    mma16(acc[mi][ni], (const uint32_t*)&aa[mi], (const uint32_t*)&bb[ni]);
        }
    }

    if (donorm) {
        __half* Ch = (__half*)jobs.out[z];
#pragma unroll
        for (int mi = 0; mi < 2; mi++) {
#pragma unroll
            for (int h = 0; h < 2; h++) {
                int m = m0 + wp * 32 + mi * 16 + h * 8 + g;
                int s = m & (N_CTX - 1);
                float v0[8], v1[8];
                float ss = 0.f;
#pragma unroll
                for (int ni = 0; ni < 8; ni++) {
                    int n = n0 + ni * 8 + 2 * t;
                    float e0 = acc[mi][ni][h * 2 + 0] + bias[n];
                    float e1 = acc[mi][ni][h * 2 + 1] + bias[n + 1];
                    v0[ni] = e0; v1[ni] = e1;
                    ss = fmaf(e0, e0, fmaf(e1, e1, ss));
                }
                ss += __shfl_xor_sync(0xffffffffu, ss, 1);
                ss += __shfl_xor_sync(0xffffffffu, ss, 2);
                float r = rsqrtf(ss * (1.0f / 64.0f) + 1.1920929e-07f);
#pragma unroll
                for (int ni = 0; ni < 8; ni++) {
                    int d = ni * 8 + 2 * t;
                    float y0 = v0[ni] * r * nw[d];
                    float y1 = v1[ni] * r * nw[d + 1];
                    int j0 = d & 31, j1 = (d + 1) & 31;
                    float o0 = y0 * g_cos[s * 32 + j0] - y1 * g_sin[s * 32 + j0];
                    float o1 = y1 * g_cos[s * 32 + j1] + y0 * g_sin[s * 32 + j1];
                    int n = n0 + d;
                    *(uint32_t*)&Ch[(size_t)m * N + n] = pack2(o0, o1);
                }
            }
        }
    } else if (ohalf) {
        __half* Ch = (__half*)jobs.out[z];
#pragma unroll
        for (int mi = 0; mi < 2; mi++) {
#pragma unroll
            for (int h = 0; h < 2; h++) {
                int m = m0 + wp * 32 + mi * 16 + h * 8 + g;
#pragma unroll
                for (int ni = 0; ni < 8; ni++) {
                    int n = n0 + ni * 8 + 2 * t;
                    float e0 = acc[mi][ni][h * 2 + 0];
                    float e1 = acc[mi][ni][h * 2 + 1];
                    if (bias) { e0 += bias[n]; e1 += bias[n + 1]; }
                    *(uint32_t*)&Ch[(size_t)m * N + n] = pack2(e0, e1);
                }
            }
        }
    } else {
        float* C = (float*)jobs.out[z];
#pragma unroll
        for (int mi = 0; mi < 2; mi++) {
#pragma unroll
            for (int h = 0; h < 2; h++) {
                int m = m0 + wp * 32 + mi * 16 + h * 8 + g;
#pragma unroll
                for (int ni = 0; ni < 8; ni++) {
                    int n = n0 + ni * 8 + 2 * t;
                    float2 v = make_float2(acc[mi][ni][h * 2 + 0], acc[mi][ni][h * 2 + 1]);
                    if (bias) { v.x += bias[n]; v.y += bias[n + 1]; }
                    if (res) {
                        float2 r = *(const float2*)&res[(size_t)m * N + n];
                        v.x += r.x; v.y += r.y;
                    }
                    *(float2*)&C[(size_t)m * N + n] = v;
                }
            }
        }
    }
}

// ---------------- fused quadratic causal attention (R14 proven) ----------------
#define QH_OFF 0
#define KH_OFF 16384
#define VH_OFF (16384 + 2 * 8192)
#define ATTN_SMEM (16384 + 2 * 8192 + 2 * 9216)   /* 51200 B */

__global__ __launch_bounds__(128)
void attn_fp16_kernel(const __half* __restrict__ Q, const __half* __restrict__ Kg,
                      const __half* __restrict__ V, __half* __restrict__ Z)
{
    extern __shared__ char smc[];
    uint4* Qh = (uint4*)(smc + QH_OFF);     // [ks4][mt8][lane32]

    const int tid = threadIdx.x;
    const int lane = tid & 31;
    const int wp = tid >> 5;
    const int g = lane >> 2, t = lane & 3;
    const int bh = blockIdx.y;
    const int b = bh >> 4, h = bh & 15;
    const int jt = (int)gridDim.x - 1 - (int)blockIdx.x;   // big tiles first
    const size_t base = (size_t)(b * N_CTX) * D_MODEL + h * 64;
    const int nkt = 2 * jt + 2;

    // ---- Q tile (128 x 64 half) -> A-frag smem, once (pure repack) ----
    {
        const int qmt = tid >> 4;
        const int qg = (tid >> 1) & 7;
        const int dh = tid & 1;
        const __half* qp0 = Q + base + (size_t)(jt * 128 + qmt * 16 + qg) * D_MODEL + dh * 32;
        const __half* qp1 = qp0 + (size_t)8 * D_MODEL;
#pragma unroll
        for (int kl = 0; kl < 2; kl++) {
            int ks = dh * 2 + kl;
            uint4 A0 = *(const uint4*)(qp0 + kl * 16);
            uint4 B0 = *(const uint4*)(qp0 + kl * 16 + 8);
            uint4 A1 = *(const uint4*)(qp1 + kl * 16);
            uint4 B1 = *(const uint4*)(qp1 + kl * 16 + 8);
            const uint32_t* a0 = (const uint32_t*)&A0;
            const uint32_t* b0 = (const uint32_t*)&B0;
            const uint32_t* a1 = (const uint32_t*)&A1;
            const uint32_t* b1 = (const uint32_t*)&B1;
            int x = ((qg >> 1) & 1) | ((ks >> 1) << 1);
#pragma unroll
            for (int tt = 0; tt < 4; tt++)
                Qh[(ks * 8 + qmt) * 32 + qg * 4 + (tt ^ x)] =
                    make_uint4(a0[tt], a1[tt], b0[tt], b1[tt]);
        }
    }

    float zacc[2][8][4];
#pragma unroll
    for (int mm = 0; mm < 2; mm++)
#pragma unroll
        for (int i = 0; i < 8; i++)
#pragma unroll
            for (int j = 0; j < 4; j++) zacc[mm][i][j] = 0.f;

    const int kr = tid & 63, ksh = tid >> 6;
    const int knt = kr >> 3, kg = kr & 7;
    const int kx = (kg >> 2) | ((knt & 1) << 1);
    const int vcp = tid >> 5;
    const int vdq = (tid >> 2) & 7;
    const int vt = tid & 3;

    const __half* kbase = Kg + base + (size_t)kr * D_MODEL + ksh * 32;
    const __half* vbase = V + base + (size_t)(16 * vcp + 2 * vt) * D_MODEL + vdq * 8;

    const float inv64 = 1.0f / 64.0f;
    const int qbase = jt * 128 + wp * 32;

    uint4 kA0, kB0, kA1, kB1, vA, vB, vC, vD;
    {
        kA0 = *(const uint4*)(kbase);
        kB0 = *(const uint4*)(kbase + 8);
        kA1 = *(const uint4*)(kbase + 16);
        kB1 = *(const uint4*)(kbase + 24);
        vA = *(const uint4*)(vbase);
        vB = *(const uint4*)(vbase + (size_t)1 * D_MODEL);
        vC = *(const uint4*)(vbase + (size_t)8 * D_MODEL);
        vD = *(const uint4*)(vbase + (size_t)9 * D_MODEL);
    }

    for (int kt = 0; kt < nkt; ++kt) {
        const int ktb = kt * 64;
        const int p = kt & 1;
        uint2* Kh = (uint2*)(smc + KH_OFF + p * 8192);
        uint2* Vh = (uint2*)(smc + VH_OFF + p * 9216);

        {
            const uint32_t* a0 = (const uint32_t*)&kA0;
            const uint32_t* b0 = (const uint32_t*)&kB0;
            const uint32_t* a1 = (const uint32_t*)&kA1;
            const uint32_t* b1 = (const uint32_t*)&kB1;
#pragma unroll
            for (int tt = 0; tt < 4; tt++) {
                int ks0 = ksh * 2;
                Kh[(ks0 * 8 + knt) * 32 + kg * 4 + (tt ^ kx)] = make_uint2(a0[tt], b0[tt]);
                Kh[((ks0 + 1) * 8 + knt) * 32 + kg * 4 + (tt ^ kx)] = make_uint2(a1[tt], b1[tt]);
            }
            const uint32_t* a = (const uint32_t*)&vA;
            const uint32_t* bb = (const uint32_t*)&vB;
            const uint32_t* c = (const uint32_t*)&vC;
            const uint32_t* d = (const uint32_t*)&vD;
#pragma unroll
            for (int i = 0; i < 8; i++) {
                int j = i >> 1;
                uint32_t sel = (i & 1) ? 0x7632u : 0x5410u;
                Vh[(vcp * 8 + vdq) * 36 + i * 4 + vt] =
                    make_uint2(__byte_perm(a[j], bb[j], sel),
                               __byte_perm(c[j], d[j], sel));
            }
        }
        __syncthreads();
        if (kt + 1 < nkt) {
            const __half* kp = kbase + (size_t)(ktb + 64) * D_MODEL;
            kA0 = *(const uint4*)(kp);
            kB0 = *(const uint4*)(kp + 8);
            kA1 = *(const uint4*)(kp + 16);
            kB1 = *(const uint4*)(kp + 24);
            const __half* vp = vbase + (size_t)(ktb + 64) * D_MODEL;
            vA = *(const uint4*)(vp);
            vB = *(const uint4*)(vp + (size_t)1 * D_MODEL);
            vC = *(const uint4*)(vp + (size_t)8 * D_MODEL);
            vD = *(const uint4*)(vp + (size_t)9 * D_MODEL);
        }

        float sacc[2][8][4];
#pragma unroll
        for (int mm = 0; mm < 2; mm++)
#pragma unroll
            for (int i = 0; i < 8; i++)
#pragma unroll
                for (int j = 0; j < 4; j++) sacc[mm][i][j] = 0.f;

#pragma unroll
        for (int ks = 0; ks < 4; ks++) {
            int qx = ((g >> 1) & 1) | ((ks >> 1) << 1);
            uint4 qa0 = Qh[(ks * 8 + wp * 2 + 0) * 32 + g * 4 + (t ^ qx)];
            uint4 qa1 = Qh[(ks * 8 + wp * 2 + 1) * 32 + g * 4 + (t ^ qx)];
#pragma unroll
            for (int nt = 0; nt < 8; nt++) {
                int xk = (g >> 2) | ((nt & 1) << 1);
                uint2 kb = Kh[(ks * 8 + nt) * 32 + g * 4 + (t ^ xk)];
                mma16(sacc[0][nt], (const uint32_t*)&qa0, (const uint32_t*)&kb);
                mma16(sacc[1][nt], (const uint32_t*)&qa1, (const uint32_t*)&kb);
            }
        }

#pragma unroll
        for (int cp = 0; cp < 4; cp++) {
            uint2 vb[8];
#pragma unroll
            for (int dn = 0; dn < 8; dn++)
                vb[dn] = Vh[(cp * 8 + dn) * 36 + g * 4 + t];
#pragma unroll
            for (int mm = 0; mm < 2; mm++) {
                int qr0 = qbase + mm * 16 + g;
                int qr1 = qr0 + 8;
                int c0 = 2 * cp, c1 = 2 * cp + 1;
                int kc0 = ktb + c0 * 8 + 2 * t;
                int kc1 = ktb + c1 * 8 + 2 * t;
                float p00 = sacc[mm][c0][0] * inv64; p00 *= p00; if (kc0 > qr0)     p00 = 0.f;
                float p01 = sacc[mm][c0][1] * inv64; p01 *= p01; if (kc0 + 1 > qr0) p01 = 0.f;
                float p02 = sacc[mm][c0][2] * inv64; p02 *= p02; if (kc0 > qr1)     p02 = 0.f;
                float p03 = sacc[mm][c0][3] * inv64; p03 *= p03; if (kc0 + 1 > qr1) p03 = 0.f;
                float p10 = sacc[mm][c1][0] * inv64; p10 *= p10; if (kc1 > qr0)     p10 = 0.f;
                float p11 = sacc[mm][c1][1] * inv64; p11 *= p11; if (kc1 + 1 > qr0) p11 = 0.f;
                float p12 = sacc[mm][c1][2] * inv64; p12 *= p12; if (kc1 > qr1)     p12 = 0.f;
                float p13 = sacc[mm][c1][3] * inv64; p13 *= p13; if (kc1 + 1 > qr1) p13 = 0.f;
                uint32_t af[4];
                af[0] = pack2(p00, p01);
                af[1] = pack2(p02, p03);
                af[2] = pack2(p10, p11);
                af[3] = pack2(p12, p13);
#pragma unroll
                for (int dn = 0; dn < 8; dn++)
                    mma16(zacc[mm][dn], af, (const uint32_t*)&vb[dn]);
            }
        }
    }

#pragma unroll
    for (int mm = 0; mm < 2; mm++) {
        int qr0 = qbase + mm * 16 + g;
        int qr1 = qr0 + 8;
#pragma unroll
        for (int dn = 0; dn < 8; dn++) {
            int col = dn * 8 + 2 * t;
            *(uint32_t*)&Z[base + (size_t)qr0 * D_MODEL + col] =
                pack2(zacc[mm][dn][0], zacc[mm][dn][1]);
            *(uint32_t*)&Z[base + (size_t)qr1 * D_MODEL + col] =
                pack2(zacc[mm][dn][2], zacc[mm][dn][3]);
        }
    }
}

// ---------------- launch ----------------
extern "C" void kernel_launch(void* const* d_in, const int* in_sizes, int n_in,
                              void* d_out, int out_size)
{
    const float* x  = (const float*)d_in[0];
    const float* Wq = (const float*)d_in[1];
    const float* bq = (const float*)d_in[2];
    const float* Wk = (const float*)d_in[3];
    const float* bk = (const float*)d_in[4];
    const float* Wv = (const float*)d_in[5];
    const float* bv = (const float*)d_in[6];
    const float* Wo = (const float*)d_in[7];
    const float* nw = (const float*)d_in[8];
    float* out = (float*)d_out;

    __half *qh, *kh, *vh, *zh, *xh, *wqh, *wkh, *wvh, *woh;
    cudaGetSymbolAddress((void**)&qh,  g_qh);
    cudaGetSymbolAddress((void**)&kh,  g_kh);
    cudaGetSymbolAddress((void**)&vh,  g_vh);
    cudaGetSymbolAddress((void**)&zh,  g_zh);
    cudaGetSymbolAddress((void**)&xh,  g_xh);
    cudaGetSymbolAddress((void**)&wqh, g_wqh);
    cudaGetSymbolAddress((void**)&wkh, g_wkh);
    cudaGetSymbolAddress((void**)&wvh, g_wvh);
    cudaGetSymbolAddress((void**)&woh, g_woh);

    cudaFuncSetAttribute(attn_fp16_kernel, cudaFuncAttributeMaxDynamicSharedMemorySize, ATTN_SMEM);

    rope_cache_kernel<<<64, 1024>>>();

    // convert x + 4 weight matrices to fp16
    CvtJobs cj;
    cj.src[0] = x;  cj.dst[0] = xh;  cj.n[0] = MTOT * D_MODEL;
    cj.src[1] = Wq; cj.dst[1] = wqh; cj.n[1] = D_MODEL * D_MODEL;
    cj.src[2] = Wk; cj.dst[2] = wkh; cj.n[2] = D_MODEL * D_MODEL;
    cj.src[3] = Wv; cj.dst[3] = wvh; cj.n[3] = D_MODEL * D_MODEL;
    cj.src[4] = Wo; cj.dst[4] = woh; cj.n[4] = D_MODEL * D_MODEL;
    cvt_kernel<<<dim3(MTOT * D_MODEL / (256 * 8), 5), 256>>>(cj);

    // QKV projections: one launch, 3 jobs; q/k fused rmsnorm+rope, all half out
    GemmJobs jq;
    jq.W[0] = wqh; jq.W[1] = wkh; jq.W[2] = wvh;
    jq.bias[0] = bq; jq.bias[1] = bk; jq.bias[2] = bv;
    jq.res[0] = nullptr; jq.res[1] = nullptr; jq.res[2] = nullptr;
    jq.out[0] = qh; jq.out[1] = kh; jq.out[2] = vh;
    jq.norm[0] = 1; jq.norm[1] = 1; jq.norm[2] = 0;
    jq.outhalf[0] = 1; jq.outhalf[1] = 1; jq.outhalf[2] = 1;
    gemm_fp16_kernel<<<dim3(D_MODEL / 64, MTOT / 128, 3), 128>>>(xh, jq, nw, MTOT, D_MODEL, D_MODEL);

    attn_fp16_kernel<<<dim3(16, 32), 128, ATTN_SMEM>>>(qh, kh, vh, zh);

    // output projection + residual (fp32 out)
    GemmJobs jo;
    jo.W[0] = woh; jo.W[1] = nullptr; jo.W[2] = nullptr;
    jo.bias[0] = nullptr; jo.bias[1] = nullptr; jo.bias[2] = nullptr;
    jo.res[0] = x; jo.res[1] = nullptr; jo.res[2] = nullptr;
    jo.out[0] = out; jo.out[1] = nullptr; jo.out[2] = nullptr;
    jo.norm[0] = 0; jo.norm[1] = 0; jo.norm[2] = 0;
    jo.outhalf[0] = 0; jo.outhalf[1] = 0; jo.outhalf[2] = 0;
    gemm_fp16_kernel<<<dim3(D_MODEL / 64, MTOT / 128, 1), 128>>>(zh, jo, nw, MTOT, D_MODEL, D_MODEL);
}

// round 17
// speedup vs baseline: 1.2021x; 1.2021x over previous
#include <cuda_runtime.h>
#include <cuda_fp16.h>
#include <math.h>
#include <stdint.h>

#define D_MODEL 1024
#define N_HEAD  16
#define D_HEAD  64
#define N_CTX   2048
#define BATCH   2
#define MTOT    (BATCH * N_CTX)   /* 4096 rows */

// ---------------- scratch ----------------
__device__ __half g_qh[MTOT * D_MODEL];
__device__ __half g_kh[MTOT * D_MODEL];
__device__ __half g_vh[MTOT * D_MODEL];
__device__ __half g_zh[MTOT * D_MODEL];
__device__ __half g_xh[MTOT * D_MODEL];
__device__ __half g_wqh[D_MODEL * D_MODEL];
__device__ __half g_wkh[D_MODEL * D_MODEL];
__device__ __half g_wvh[D_MODEL * D_MODEL];
__device__ __half g_woh[D_MODEL * D_MODEL];
__device__ float  g_cos[N_CTX * 32];
__device__ float  g_sin[N_CTX * 32];

// ---------------- helpers ----------------
__device__ __forceinline__ uint32_t pack2(float x, float y) {
    __half2 h = __floats2half2_rn(x, y);
    return *(uint32_t*)&h;
}

// fp16 m16n8k16
__device__ __forceinline__ void mma16(float c[4], const uint32_t* a, const uint32_t* b) {
    asm volatile(
        "mma.sync.aligned.m16n8k16.row.col.f32.f16.f16.f32 "
        "{%0,%1,%2,%3}, {%4,%5,%6,%7}, {%8,%9}, {%0,%1,%2,%3};\n"
        : "+f"(c[0]), "+f"(c[1]), "+f"(c[2]), "+f"(c[3])
        : "r"(a[0]), "r"(a[1]), "r"(a[2]), "r"(a[3]), "r"(b[0]), "r"(b[1]));
}

// ---------------- RoPE table ----------------
__global__ void rope_cache_kernel() {
    int i = blockIdx.x * blockDim.x + threadIdx.x;
    int t = i >> 5;
    int j = i & 31;
    float invf = (float)pow(10000.0, -(double)j / 32.0);
    double ang = (double)t * (double)invf;
    double sv, cv;
    sincos(ang, &sv, &cv);
    g_cos[i] = (float)cv;
    g_sin[i] = (float)sv;
}

// ---------------- fp32 -> fp16 conversion (x + 4 weight matrices) ----------------
struct CvtJobs {
    const float* src[5];
    __half*      dst[5];
    int          n[5];
};

__global__ __launch_bounds__(256)
void cvt_kernel(CvtJobs j) {
    int z = blockIdx.y;
    int i = (blockIdx.x * 256 + threadIdx.x) * 8;
    if (i >= j.n[z]) return;
    float4 f0 = *(const float4*)(j.src[z] + i);
    float4 f1 = *(const float4*)(j.src[z] + i + 4);
    uint4 o;
    o.x = pack2(f0.x, f0.y); o.y = pack2(f0.z, f0.w);
    o.z = pack2(f1.x, f1.y); o.w = pack2(f1.z, f1.w);
    *(uint4*)(j.dst[z] + i) = o;
}

// ---------------- FP16 GEMM, half in, double-buffered; half or float out ----------------
// R14 proven core; prefetch LDGs hoisted BEFORE the barrier (store->LDG->bar->compute).
struct GemmJobs {
    const __half* W[3];
    const float*  bias[3];
    const float*  res[3];
    void*         out[3];
    int           norm[3];      // 1 => fused rmsnorm+rope epilogue, half out
    int           outhalf[3];   // 1 => half out
};

__global__ __launch_bounds__(256, 2)
void gemm_fp16_kernel(const __half* __restrict__ A, GemmJobs jobs,
                      const float* __restrict__ nw, int M, int N, int K)
{
    __shared__ __align__(16) uint32_t As[2][2048];
    __shared__ __align__(16) uint32_t Bs[2][2048];

    const int z = blockIdx.z;
    const __half* W   = jobs.W[z];
    const float* bias = jobs.bias[z];
    const float* res  = jobs.res[z];
    const int    donorm = jobs.norm[z];
    const int    ohalf  = jobs.outhalf[z];

    const int tid = threadIdx.x;
    const int lane = tid & 31;
    const int wid = tid >> 5;
    const int wm = wid & 3, wn = wid >> 2;
    const int m0 = blockIdx.y * 128, n0 = blockIdx.x * 128;

    const int amt = tid >> 5, ag = (tid >> 2) & 7, aks = tid & 3;
    const int aksh = aks >> 1, ahk = aks & 1;
    const int axor = ((ag >> 1) & 1) | (aksh << 1);
    const __half* Ap = A + (size_t)(m0 + amt * 16 + ag) * K + aks * 8;
    const int bnt = ((tid >> 5) << 1) | (tid & 1);
    const int bg = (tid >> 2) & 7;
    const int bks = (tid >> 1) & 1;
    const int bxr = (tid & 1) | (bks << 1);
    const __half* Wp = W + (size_t)(n0 + bnt * 8 + bg) * K + bks * 16;

    float acc[2][8][4];
#pragma unroll
    for (int mi = 0; mi < 2; mi++)
#pragma unroll
        for (int ni = 0; ni < 8; ni++)
#pragma unroll
            for (int e = 0; e < 4; e++) acc[mi][ni][e] = 0.f;

    const int NCH = K / 32;
    uint4 a_lo = *(const uint4*)(Ap);
    uint4 a_hi = *(const uint4*)(Ap + (size_t)8 * K);
    uint4 w_lo = *(const uint4*)(Wp);
    uint4 w_hi = *(const uint4*)(Wp + 8);

    for (int kt = 0; kt < NCH; kt++) {
        const int p = kt & 1;
        {
            const uint32_t* alo = (const uint32_t*)&a_lo;
            const uint32_t* ahi = (const uint32_t*)&a_hi;
            const uint32_t* wlo = (const uint32_t*)&w_lo;
            const uint32_t* whi = (const uint32_t*)&w_hi;
#pragma unroll
            for (int t = 0; t < 4; t++) {
                int aslot = (aksh * 8 + amt) * 32 + 4 * ag + (t ^ axor);
                *(uint2*)&As[p][aslot * 4 + 2 * ahk] = make_uint2(alo[t], ahi[t]);
                int bslot = (bks * 16 + bnt) * 32 + 4 * bg + (t ^ bxr);
                *(uint2*)&Bs[p][bslot * 2] = make_uint2(wlo[t], whi[t]);
            }
        }
        // prefetch next chunk BEFORE the barrier: loads issue during barrier skew
        if (kt + 1 < NCH) {
            int off = (kt + 1) * 32;
            a_lo = *(const uint4*)(Ap + off);
            a_hi = *(const uint4*)(Ap + off + (size_t)8 * K);
            w_lo = *(const uint4*)(Wp + off);
            w_hi = *(const uint4*)(Wp + off + 8);
        }
        __syncthreads();
#pragma unroll
        for (int ks = 0; ks < 2; ks++) {
            uint2 bb[8];
#pragma unroll
            for (int ni = 0; ni < 8; ni++) {
                int nt = wn * 8 + ni;
                int x = (nt & 1) | (ks << 1);
                int s = (ks * 16 + nt) * 32 + (lane & 28) + ((lane & 3) ^ x);
                bb[ni] = *(const uint2*)&Bs[p][s * 2];
            }
            int xa = ((lane >> 3) & 1) | (ks << 1);
            uint4 aa[2];
#pragma unroll
            for (int mi = 0; mi < 2; mi++) {
                int s = (ks * 8 + wm * 2 + mi) * 32 + (lane & 28) + ((lane & 3) ^ xa);
                aa[mi] = *(const uint4*)&As[p][s * 4];
            }
#pragma unroll
            for (int mi = 0; mi < 2; mi++)
#pragma unroll
                for (int ni = 0; ni < 8; ni++)
                    mma16(acc[mi][ni], (const uint32_t*)&aa[mi], (const uint32_t*)&bb[ni]);
        }
    }

    const int g = lane >> 2, t = lane & 3;
    if (donorm) {
        __half* Ch = (__half*)jobs.out[z];
#pragma unroll
        for (int mi = 0; mi < 2; mi++) {
#pragma unroll
            for (int h = 0; h < 2; h++) {
                int m = m0 + wm * 32 + mi * 16 + h * 8 + g;
                int s = m & (N_CTX - 1);
                float v0[8], v1[8];
                float ss = 0.f;
#pragma unroll
                for (int ni = 0; ni < 8; ni++) {
                    int n = n0 + wn * 64 + ni * 8 + 2 * t;
                    float e0 = acc[mi][ni][h * 2 + 0] + bias[n];
                    float e1 = acc[mi][ni][h * 2 + 1] + bias[n + 1];
                    v0[ni] = e0; v1[ni] = e1;
                    ss = fmaf(e0, e0, fmaf(e1, e1, ss));
                }
                ss += __shfl_xor_sync(0xffffffffu, ss, 1);
                ss += __shfl_xor_sync(0xffffffffu, ss, 2);
                float r = rsqrtf(ss * (1.0f / 64.0f) + 1.1920929e-07f);
#pragma unroll
                for (int ni = 0; ni < 8; ni++) {
                    int d = ni * 8 + 2 * t;
                    float y0 = v0[ni] * r * nw[d];
                    float y1 = v1[ni] * r * nw[d + 1];
                    int j0 = d & 31, j1 = (d + 1) & 31;
                    float o0 = y0 * g_cos[s * 32 + j0] - y1 * g_sin[s * 32 + j0];
                    float o1 = y1 * g_cos[s * 32 + j1] + y0 * g_sin[s * 32 + j1];
                    int n = n0 + wn * 64 + d;
                    *(uint32_t*)&Ch[(size_t)m * N + n] = pack2(o0, o1);
                }
            }
        }
    } else if (ohalf) {
        __half* Ch = (__half*)jobs.out[z];
#pragma unroll
        for (int mi = 0; mi < 2; mi++) {
#pragma unroll
            for (int h = 0; h < 2; h++) {
                int m = m0 + wm * 32 + mi * 16 + h * 8 + g;
#pragma unroll
                for (int ni = 0; ni < 8; ni++) {
                    int n = n0 + wn * 64 + ni * 8 + 2 * t;
                    float e0 = acc[mi][ni][h * 2 + 0];
                    float e1 = acc[mi][ni][h * 2 + 1];
                    if (bias) { e0 += bias[n]; e1 += bias[n + 1]; }
                    *(uint32_t*)&Ch[(size_t)m * N + n] = pack2(e0, e1);
                }
            }
        }
    } else {
        float* C = (float*)jobs.out[z];
#pragma unroll
        for (int mi = 0; mi < 2; mi++) {
#pragma unroll
            for (int h = 0; h < 2; h++) {
                int m = m0 + wm * 32 + mi * 16 + h * 8 + g;
#pragma unroll
                for (int ni = 0; ni < 8; ni++) {
                    int n = n0 + wn * 64 + ni * 8 + 2 * t;
                    float2 v = make_float2(acc[mi][ni][h * 2 + 0], acc[mi][ni][h * 2 + 1]);
                    if (bias) { v.x += bias[n]; v.y += bias[n + 1]; }
                    if (res) {
                        float2 r = *(const float2*)&res[(size_t)m * N + n];
                        v.x += r.x; v.y += r.y;
                    }
                    *(float2*)&C[(size_t)m * N + n] = v;
                }
            }
        }
    }
}

// ---------------- fused quadratic causal attention (R14 proven, prefetch hoisted) ----------------
#define QH_OFF 0
#define KH_OFF 16384
#define VH_OFF (16384 + 2 * 8192)
#define ATTN_SMEM (16384 + 2 * 8192 + 2 * 9216)   /* 51200 B */

__global__ __launch_bounds__(128)
void attn_fp16_kernel(const __half* __restrict__ Q, const __half* __restrict__ Kg,
                      const __half* __restrict__ V, __half* __restrict__ Z)
{
    extern __shared__ char smc[];
    uint4* Qh = (uint4*)(smc + QH_OFF);     // [ks4][mt8][lane32]

    const int tid = threadIdx.x;
    const int lane = tid & 31;
    const int wp = tid >> 5;
    const int g = lane >> 2, t = lane & 3;
    const int bh = blockIdx.y;
    const int b = bh >> 4, h = bh & 15;
    const int jt = (int)gridDim.x - 1 - (int)blockIdx.x;   // big tiles first
    const size_t base = (size_t)(b * N_CTX) * D_MODEL + h * 64;
    const int nkt = 2 * jt + 2;

    // ---- Q tile (128 x 64 half) -> A-frag smem, once (pure repack) ----
    {
        const int qmt = tid >> 4;
        const int qg = (tid >> 1) & 7;
        const int dh = tid & 1;
        const __half* qp0 = Q + base + (size_t)(jt * 128 + qmt * 16 + qg) * D_MODEL + dh * 32;
        const __half* qp1 = qp0 + (size_t)8 * D_MODEL;
#pragma unroll
        for (int kl = 0; kl < 2; kl++) {
            int ks = dh * 2 + kl;
            uint4 A0 = *(const uint4*)(qp0 + kl * 16);
            uint4 B0 = *(const uint4*)(qp0 + kl * 16 + 8);
            uint4 A1 = *(const uint4*)(qp1 + kl * 16);
            uint4 B1 = *(const uint4*)(qp1 + kl * 16 + 8);
            const uint32_t* a0 = (const uint32_t*)&A0;
            const uint32_t* b0 = (const uint32_t*)&B0;
            const uint32_t* a1 = (const uint32_t*)&A1;
            const uint32_t* b1 = (const uint32_t*)&B1;
            int x = ((qg >> 1) & 1) | ((ks >> 1) << 1);
#pragma unroll
            for (int tt = 0; tt < 4; tt++)
                Qh[(ks * 8 + qmt) * 32 + qg * 4 + (tt ^ x)] =
                    make_uint4(a0[tt], a1[tt], b0[tt], b1[tt]);
        }
    }

    float zacc[2][8][4];
#pragma unroll
    for (int mm = 0; mm < 2; mm++)
#pragma unroll
        for (int i = 0; i < 8; i++)
#pragma unroll
            for (int j = 0; j < 4; j++) zacc[mm][i][j] = 0.f;

    const int kr = tid & 63, ksh = tid >> 6;
    const int knt = kr >> 3, kg = kr & 7;
    const int kx = (kg >> 2) | ((knt & 1) << 1);
    const int vcp = tid >> 5;
    const int vdq = (tid >> 2) & 7;
    const int vt = tid & 3;

    const __half* kbase = Kg + base + (size_t)kr * D_MODEL + ksh * 32;
    const __half* vbase = V + base + (size_t)(16 * vcp + 2 * vt) * D_MODEL + vdq * 8;

    const float inv64 = 1.0f / 64.0f;
    const int qbase = jt * 128 + wp * 32;

    uint4 kA0, kB0, kA1, kB1, vA, vB, vC, vD;
    {
        kA0 = *(const uint4*)(kbase);
        kB0 = *(const uint4*)(kbase + 8);
        kA1 = *(const uint4*)(kbase + 16);
        kB1 = *(const uint4*)(kbase + 24);
        vA = *(const uint4*)(vbase);
        vB = *(const uint4*)(vbase + (size_t)1 * D_MODEL);
        vC = *(const uint4*)(vbase + (size_t)8 * D_MODEL);
        vD = *(const uint4*)(vbase + (size_t)9 * D_MODEL);
    }

    for (int kt = 0; kt < nkt; ++kt) {
        const int ktb = kt * 64;
        const int p = kt & 1;
        uint2* Kh = (uint2*)(smc + KH_OFF + p * 8192);
        uint2* Vh = (uint2*)(smc + VH_OFF + p * 9216);

        // ---- store staged K/V into buffer p ----
        {
            const uint32_t* a0 = (const uint32_t*)&kA0;
            const uint32_t* b0 = (const uint32_t*)&kB0;
            const uint32_t* a1 = (const uint32_t*)&kA1;
            const uint32_t* b1 = (const uint32_t*)&kB1;
#pragma unroll
            for (int tt = 0; tt < 4; tt++) {
                int ks0 = ksh * 2;
                Kh[(ks0 * 8 + knt) * 32 + kg * 4 + (tt ^ kx)] = make_uint2(a0[tt], b0[tt]);
                Kh[((ks0 + 1) * 8 + knt) * 32 + kg * 4 + (tt ^ kx)] = make_uint2(a1[tt], b1[tt]);
            }
            const uint32_t* a = (const uint32_t*)&vA;
            const uint32_t* bb = (const uint32_t*)&vB;
            const uint32_t* c = (const uint32_t*)&vC;
            const uint32_t* d = (const uint32_t*)&vD;
#pragma unroll
            for (int i = 0; i < 8; i++) {
                int j = i >> 1;
                uint32_t sel = (i & 1) ? 0x7632u : 0x5410u;
                Vh[(vcp * 8 + vdq) * 36 + i * 4 + vt] =
                    make_uint2(__byte_perm(a[j], bb[j], sel),
                               __byte_perm(c[j], d[j], sel));
            }
        }
        // ---- prefetch next tile BEFORE the barrier ----
        if (kt + 1 < nkt) {
            const __half* kp = kbase + (size_t)(ktb + 64) * D_MODEL;
            kA0 = *(const uint4*)(kp);
            kB0 = *(const uint4*)(kp + 8);
            kA1 = *(const uint4*)(kp + 16);
            kB1 = *(const uint4*)(kp + 24);
            const __half* vp = vbase + (size_t)(ktb + 64) * D_MODEL;
            vA = *(const uint4*)(vp);
            vB = *(const uint4*)(vp + (size_t)1 * D_MODEL);
            vC = *(const uint4*)(vp + (size_t)8 * D_MODEL);
            vD = *(const uint4*)(vp + (size_t)9 * D_MODEL);
        }
        __syncthreads();   // buffer p written (also orders Q store at kt=0)

        // ---- GEMM1: S[32 x 64] per warp ----
        float sacc[2][8][4];
#pragma unroll
        for (int mm = 0; mm < 2; mm++)
#pragma unroll
            for (int i = 0; i < 8; i++)
#pragma unroll
                for (int j = 0; j < 4; j++) sacc[mm][i][j] = 0.f;

#pragma unroll
        for (int ks = 0; ks < 4; ks++) {
            int qx = ((g >> 1) & 1) | ((ks >> 1) << 1);
            uint4 qa0 = Qh[(ks * 8 + wp * 2 + 0) * 32 + g * 4 + (t ^ qx)];
            uint4 qa1 = Qh[(ks * 8 + wp * 2 + 1) * 32 + g * 4 + (t ^ qx)];
#pragma unroll
            for (int nt = 0; nt < 8; nt++) {
                int xk = (g >> 2) | ((nt & 1) << 1);
                uint2 kb = Kh[(ks * 8 + nt) * 32 + g * 4 + (t ^ xk)];
                mma16(sacc[0][nt], (const uint32_t*)&qa0, (const uint32_t*)&kb);
                mma16(sacc[1][nt], (const uint32_t*)&qa1, (const uint32_t*)&kb);
            }
        }

        // ---- P = (S/64)^2 * causal -> direct A-frag pack; GEMM2 ----
#pragma unroll
        for (int cp = 0; cp < 4; cp++) {
            uint2 vb[8];
#pragma unroll
            for (int dn = 0; dn < 8; dn++)
                vb[dn] = Vh[(cp * 8 + dn) * 36 + g * 4 + t];
#pragma unroll
            for (int mm = 0; mm < 2; mm++) {
                int qr0 = qbase + mm * 16 + g;
                int qr1 = qr0 + 8;
                int c0 = 2 * cp, c1 = 2 * cp + 1;
                int kc0 = ktb + c0 * 8 + 2 * t;
                int kc1 = ktb + c1 * 8 + 2 * t;
                float p00 = sacc[mm][c0][0] * inv64; p00 *= p00; if (kc0 > qr0)     p00 = 0.f;
                float p01 = sacc[mm][c0][1] * inv64; p01 *= p01; if (kc0 + 1 > qr0) p01 = 0.f;
                float p02 = sacc[mm][c0][2] * inv64; p02 *= p02; if (kc0 > qr1)     p02 = 0.f;
                float p03 = sacc[mm][c0][3] * inv64; p03 *= p03; if (kc0 + 1 > qr1) p03 = 0.f;
                float p10 = sacc[mm][c1][0] * inv64; p10 *= p10; if (kc1 > qr0)     p10 = 0.f;
                float p11 = sacc[mm][c1][1] * inv64; p11 *= p11; if (kc1 + 1 > qr0) p11 = 0.f;
                float p12 = sacc[mm][c1][2] * inv64; p12 *= p12; if (kc1 > qr1)     p12 = 0.f;
                float p13 = sacc[mm][c1][3] * inv64; p13 *= p13; if (kc1 + 1 > qr1) p13 = 0.f;
                uint32_t af[4];
                af[0] = pack2(p00, p01);
                af[1] = pack2(p02, p03);
                af[2] = pack2(p10, p11);
                af[3] = pack2(p12, p13);
#pragma unroll
                for (int dn = 0; dn < 8; dn++)
                    mma16(zacc[mm][dn], af, (const uint32_t*)&vb[dn]);
            }
        }
    }

    // ---- write Z (fp16) ----
#pragma unroll
    for (int mm = 0; mm < 2; mm++) {
        int qr0 = qbase + mm * 16 + g;
        int qr1 = qr0 + 8;
#pragma unroll
        for (int dn = 0; dn < 8; dn++) {
            int col = dn * 8 + 2 * t;
            *(uint32_t*)&Z[base + (size_t)qr0 * D_MODEL + col] =
                pack2(zacc[mm][dn][0], zacc[mm][dn][1]);
            *(uint32_t*)&Z[base + (size_t)qr1 * D_MODEL + col] =
                pack2(zacc[mm][dn][2], zacc[mm][dn][3]);
        }
    }
}

// ---------------- launch ----------------
extern "C" void kernel_launch(void* const* d_in, const int* in_sizes, int n_in,
                              void* d_out, int out_size)
{
    const float* x  = (const float*)d_in[0];
    const float* Wq = (const float*)d_in[1];
    const float* bq = (const float*)d_in[2];
    const float* Wk = (const float*)d_in[3];
    const float* bk = (const float*)d_in[4];
    const float* Wv = (const float*)d_in[5];
    const float* bv = (const float*)d_in[6];
    const float* Wo = (const float*)d_in[7];
    const float* nw = (const float*)d_in[8];
    float* out = (float*)d_out;

    __half *qh, *kh, *vh, *zh, *xh, *wqh, *wkh, *wvh, *woh;
    cudaGetSymbolAddress((void**)&qh,  g_qh);
    cudaGetSymbolAddress((void**)&kh,  g_kh);
    cudaGetSymbolAddress((void**)&vh,  g_vh);
    cudaGetSymbolAddress((void**)&zh,  g_zh);
    cudaGetSymbolAddress((void**)&xh,  g_xh);
    cudaGetSymbolAddress((void**)&wqh, g_wqh);
    cudaGetSymbolAddress((void**)&wkh, g_wkh);
    cudaGetSymbolAddress((void**)&wvh, g_wvh);
    cudaGetSymbolAddress((void**)&woh, g_woh);

    cudaFuncSetAttribute(attn_fp16_kernel, cudaFuncAttributeMaxDynamicSharedMemorySize, ATTN_SMEM);

    rope_cache_kernel<<<64, 1024>>>();

    // convert x + 4 weight matrices to fp16
    CvtJobs cj;
    cj.src[0] = x;  cj.dst[0] = xh;  cj.n[0] = MTOT * D_MODEL;
    cj.src[1] = Wq; cj.dst[1] = wqh; cj.n[1] = D_MODEL * D_MODEL;
    cj.src[2] = Wk; cj.dst[2] = wkh; cj.n[2] = D_MODEL * D_MODEL;
    cj.src[3] = Wv; cj.dst[3] = wvh; cj.n[3] = D_MODEL * D_MODEL;
    cj.src[4] = Wo; cj.dst[4] = woh; cj.n[4] = D_MODEL * D_MODEL;
    cvt_kernel<<<dim3(MTOT * D_MODEL / (256 * 8), 5), 256>>>(cj);

    // QKV projections: one launch, 3 jobs; q/k fused rmsnorm+rope, all half out
    GemmJobs jq;
    jq.W[0] = wqh; jq.W[1] = wkh; jq.W[2] = wvh;
    jq.bias[0] = bq; jq.bias[1] = bk; jq.bias[2] = bv;
    jq.res[0] = nullptr; jq.res[1] = nullptr; jq.res[2] = nullptr;
    jq.out[0] = qh; jq.out[1] = kh; jq.out[2] = vh;
    jq.norm[0] = 1; jq.norm[1] = 1; jq.norm[2] = 0;
    jq.outhalf[0] = 1; jq.outhalf[1] = 1; jq.outhalf[2] = 1;
    gemm_fp16_kernel<<<dim3(D_MODEL / 128, MTOT / 128, 3), 256>>>(xh, jq, nw, MTOT, D_MODEL, D_MODEL);

    attn_fp16_kernel<<<dim3(16, 32), 128, ATTN_SMEM>>>(qh, kh, vh, zh);

    // output projection + residual (fp32 out)
    GemmJobs jo;
    jo.W[0] = woh; jo.W[1] = nullptr; jo.W[2] = nullptr;
    jo.bias[0] = nullptr; jo.bias[1] = nullptr; jo.bias[2] = nullptr;
    jo.res[0] = x; jo.res[1] = nullptr; jo.res[2] = nullptr;
    jo.out[0] = out; jo.out[1] = nullptr; jo.out[2] = nullptr;
    jo.norm[0] = 0; jo.norm[1] = 0; jo.norm[2] = 0;
    jo.outhalf[0] = 0; jo.outhalf[1] = 0; jo.outhalf[2] = 0;
    gemm_fp16_kernel<<<dim3(D_MODEL / 128, MTOT / 128, 1), 256>>>(zh, jo, nw, MTOT, D_MODEL, D_MODEL);
}